// round 12
// baseline (speedup 1.0000x reference)
#include <cuda_runtime.h>
#include <cuda_bf16.h>
#include <cstdint>

#define BN 8
#define TN 2048
#define CN 1024
#define HN 128

// bf16 split scratch (allocation-free rule: __device__ globals)
__device__ __align__(16) __nv_bfloat16 g_kh[BN * TN * HN];   // k hi [b*T+t][h]  (q == k)
__device__ __align__(16) __nv_bfloat16 g_kl[BN * TN * HN];   // k lo
__device__ __align__(16) __nv_bfloat16 g_vh[BN * HN * TN];   // v^T hi [b][h][t]
__device__ __align__(16) __nv_bfloat16 g_vl[BN * HN * TN];   // v^T lo

// ---------------------------------------------------------------------------
__device__ __forceinline__ uint32_t smem_u32(const void* p) {
    uint32_t a;
    asm("{ .reg .u64 t; cvta.to.shared.u64 t, %1; cvt.u32.u64 %0, t; }" : "=r"(a) : "l"(p));
    return a;
}
__device__ __forceinline__ float fex2(float x) {
    float r; asm("ex2.approx.f32 %0, %1;" : "=f"(r) : "f"(x)); return r;
}
__device__ __forceinline__ void mma_bf16(float* d, const uint32_t* a, const uint32_t* b) {
    asm volatile("mma.sync.aligned.m16n8k16.row.col.f32.bf16.bf16.f32 "
        "{%0,%1,%2,%3}, {%4,%5,%6,%7}, {%8,%9}, {%0,%1,%2,%3};"
        : "+f"(d[0]), "+f"(d[1]), "+f"(d[2]), "+f"(d[3])
        : "r"(a[0]), "r"(a[1]), "r"(a[2]), "r"(a[3]), "r"(b[0]), "r"(b[1]));
}
__device__ __forceinline__ void ldmx4(uint32_t* r, uint32_t a) {
    asm volatile("ldmatrix.sync.aligned.m8n8.x4.shared.b16 {%0,%1,%2,%3}, [%4];"
        : "=r"(r[0]), "=r"(r[1]), "=r"(r[2]), "=r"(r[3]) : "r"(a));
}
__device__ __forceinline__ uint32_t aAddr(int r0, int kbyte, int stride, int lane) {
    int row = r0 + (lane & 7) + (lane & 8);
    int bo  = kbyte + ((lane >> 4) << 4);
    return (uint32_t)(row * stride + bo);
}
__device__ __forceinline__ uint32_t bAddr(int n0, int kbyte, int stride, int lane) {
    int row = n0 + (lane & 7) + ((lane & 16) >> 1);
    int bo  = kbyte + ((lane & 8) << 1);
    return (uint32_t)(row * stride + bo);
}
__device__ __forceinline__ void spl(float a, float b, uint32_t& H, uint32_t& L) {
    __nv_bfloat162 h = __floats2bfloat162_rn(a, b);
    H = *reinterpret_cast<uint32_t*>(&h);
    float ra = a - __bfloat162float(__low2bfloat16(h));
    float rb = b - __bfloat162float(__high2bfloat16(h));
    __nv_bfloat162 l = __floats2bfloat162_rn(ra, rb);
    L = *reinterpret_cast<uint32_t*>(&l);
}

// ---------------------------------------------------------------------------
// Projection (R8 known-good): grid (128, 2); 128 t-rows x 128 h of k (y=0) or
// v (y=1); in-kernel fp32->bf16 split; 3-pass mma over BK=32.
// ---------------------------------------------------------------------------
#define PX_H 0
#define PX_L 10240
#define PW_H 20480
#define PW_L 30720
#define P_STG 40960
#define P_SMEM (40960 + 128 * 132 * 4)   // 108544

__global__ __launch_bounds__(256, 2) void proj_kernel(
    const float* __restrict__ x,
    const float* __restrict__ Wk,
    const float* __restrict__ Wv)
{
    extern __shared__ char smc[];
    const uint32_t sb = smem_u32(smc);
    const int tid = threadIdx.x;
    const int lane = tid & 31, warp = tid >> 5;
    const int t0 = blockIdx.x * 128;
    const int mode = blockIdx.y;
    const float* __restrict__ W = (mode == 0) ? Wk : Wv;

    const int m0 = (warp >> 1) * 32;
    const int n0 = (warp & 1) * 64;

    float acc[2][8][4];
#pragma unroll
    for (int i = 0; i < 2; ++i)
#pragma unroll
        for (int j = 0; j < 8; ++j)
#pragma unroll
            for (int q = 0; q < 4; ++q) acc[i][j][q] = 0.f;

    const int frow = tid >> 1, fcb = (tid & 1) * 16;

    for (int c0 = 0; c0 < CN; c0 += 32) {
        __syncthreads();
        {
            const float* xr = x + (size_t)(t0 + frow) * CN + c0 + fcb;
            const float* wr = W + (size_t)frow * CN + c0 + fcb;
#pragma unroll
            for (int i = 0; i < 4; ++i) {
                float4 f = *(const float4*)(xr + i * 4);
                uint32_t h0, l0, h1, l1;
                spl(f.x, f.y, h0, l0); spl(f.z, f.w, h1, l1);
                *(uint2*)(smc + PX_H + frow * 80 + (fcb + i * 4) * 2) = make_uint2(h0, h1);
                *(uint2*)(smc + PX_L + frow * 80 + (fcb + i * 4) * 2) = make_uint2(l0, l1);
                f = *(const float4*)(wr + i * 4);
                spl(f.x, f.y, h0, l0); spl(f.z, f.w, h1, l1);
                *(uint2*)(smc + PW_H + frow * 80 + (fcb + i * 4) * 2) = make_uint2(h0, h1);
                *(uint2*)(smc + PW_L + frow * 80 + (fcb + i * 4) * 2) = make_uint2(l0, l1);
            }
        }
        __syncthreads();
#pragma unroll
        for (int kk = 0; kk < 2; ++kk) {
            const int kb = kk * 32;
            uint32_t ah[2][4], al[2][4];
            ldmx4(ah[0], sb + PX_H + aAddr(m0,      kb, 80, lane));
            ldmx4(ah[1], sb + PX_H + aAddr(m0 + 16, kb, 80, lane));
            ldmx4(al[0], sb + PX_L + aAddr(m0,      kb, 80, lane));
            ldmx4(al[1], sb + PX_L + aAddr(m0 + 16, kb, 80, lane));
#pragma unroll
            for (int np = 0; np < 4; ++np) {
                uint32_t bh[4], bl[4];
                ldmx4(bh, sb + PW_H + bAddr(n0 + np * 16, kb, 80, lane));
                ldmx4(bl, sb + PW_L + bAddr(n0 + np * 16, kb, 80, lane));
#pragma unroll
                for (int mi = 0; mi < 2; ++mi) {
                    mma_bf16(acc[mi][np * 2],     ah[mi], bh);
                    mma_bf16(acc[mi][np * 2],     ah[mi], bl);
                    mma_bf16(acc[mi][np * 2],     al[mi], bh);
                    mma_bf16(acc[mi][np * 2 + 1], ah[mi], bh + 2);
                    mma_bf16(acc[mi][np * 2 + 1], ah[mi], bl + 2);
                    mma_bf16(acc[mi][np * 2 + 1], al[mi], bh + 2);
                }
            }
        }
    }

    if (mode == 0) {
#pragma unroll
        for (int mi = 0; mi < 2; ++mi)
#pragma unroll
            for (int ni = 0; ni < 8; ++ni) {
                int gr  = t0 + m0 + mi * 16 + (lane >> 2);
                int col = n0 + ni * 8 + (lane & 3) * 2;
                uint32_t H, L;
                spl(acc[mi][ni][0], acc[mi][ni][1], H, L);
                *(uint32_t*)(g_kh + (size_t)gr * HN + col) = H;
                *(uint32_t*)(g_kl + (size_t)gr * HN + col) = L;
                spl(acc[mi][ni][2], acc[mi][ni][3], H, L);
                *(uint32_t*)(g_kh + (size_t)(gr + 8) * HN + col) = H;
                *(uint32_t*)(g_kl + (size_t)(gr + 8) * HN + col) = L;
            }
    } else {
        float* stg = (float*)(smc + P_STG);
#pragma unroll
        for (int mi = 0; mi < 2; ++mi)
#pragma unroll
            for (int ni = 0; ni < 8; ++ni) {
                int r = m0 + mi * 16 + (lane >> 2);
                int c = n0 + ni * 8 + (lane & 3) * 2;
                *(float2*)&stg[r * 132 + c]       = make_float2(acc[mi][ni][0], acc[mi][ni][1]);
                *(float2*)&stg[(r + 8) * 132 + c] = make_float2(acc[mi][ni][2], acc[mi][ni][3]);
            }
        __syncthreads();
        const int h = tid >> 1, th = (tid & 1) * 64;
        const int bb = t0 >> 11, tt0 = t0 & (TN - 1);
        __nv_bfloat16* dh = g_vh + ((size_t)bb * HN + h) * TN + tt0 + th;
        __nv_bfloat16* dl = g_vl + ((size_t)bb * HN + h) * TN + tt0 + th;
#pragma unroll
        for (int g = 0; g < 8; ++g) {
            uint32_t H[4], L[4];
#pragma unroll
            for (int j = 0; j < 4; ++j) {
                float a = stg[(th + g * 8 + j * 2) * 132 + h];
                float b = stg[(th + g * 8 + j * 2 + 1) * 132 + h];
                spl(a, b, H[j], L[j]);
            }
            *(uint4*)(dh + g * 8) = make_uint4(H[0], H[1], H[2], H[3]);
            *(uint4*)(dl + g * 8) = make_uint4(L[0], L[1], L[2], L[3]);
        }
    }
}

// ---------------------------------------------------------------------------
// Attention, h-split for occupancy: grid (16 pairs, 2 h-halves, 8 batches).
// Block computes its q-pair's output for h in [hh*64, hh*64+64). S recomputed
// per h-block (+25% total MMA) but O shrinks to 32 regs and Q frags are
// reloaded from smem => ~128 regs => 2 CTAs/SM (16 warps). 8 warps =
// 4 row-groups x 2 key-halves; key-half partials combined in smem.
// ---------------------------------------------------------------------------
#define AQ_H 0
#define AQ_L 17408
#define AK_H 34816
#define AK_L 52224
#define AV_H 69632
#define AV_L 78848
#define A_SMEM 88064
#define AP_O  AK_H            // float [2][64][64] = 32768 B (overlays K)
#define AP_L  (AK_H + 32768)  // float [2][64]

__global__ __launch_bounds__(256, 2) void attn_kernel(float* __restrict__ out)
{
    extern __shared__ char smc[];
    const uint32_t sb = smem_u32(smc);
    const int tid = threadIdx.x;
    const int lane = tid & 31, warp = tid >> 5;
    const int wm = warp & 3;          // row group: q-rows 16*wm .. +15
    const int wk = warp >> 2;         // key half: keys 32*wk .. +31
    const int bx = blockIdx.x;        // pair index 0..15
    const int hh = blockIdx.y;        // h half
    const int b  = blockIdx.z;
    const float SC = 1.4426950408889634f / 32.0f;   // log2(e) * C^-0.5

#pragma unroll 1
    for (int ph = 0; ph < 2; ++ph) {
        const int qt = ph ? bx : (31 - bx);
        const int q0 = qt * 64;
        const int nkt = qt + 1;

        // fill Q tile: 64 rows x 128 bf16 hi/lo, stride 272
        {
            const int row = tid >> 2, qb = tid & 3;
            const __nv_bfloat16* srch = g_kh + (size_t)(b * TN + q0 + row) * HN + qb * 32;
            const __nv_bfloat16* srcl = g_kl + (size_t)(b * TN + q0 + row) * HN + qb * 32;
#pragma unroll
            for (int i = 0; i < 4; ++i) {
                *(uint4*)(smc + AQ_H + row * 272 + qb * 64 + i * 16) = *(const uint4*)(srch + i * 8);
                *(uint4*)(smc + AQ_L + row * 272 + qb * 64 + i * 16) = *(const uint4*)(srcl + i * 8);
            }
        }

        float o[8][4];
#pragma unroll
        for (int i = 0; i < 8; ++i)
#pragma unroll
            for (int j = 0; j < 4; ++j) o[i][j] = 0.f;
        float ls0 = 0.f, ls1 = 0.f;
        const int qr0 = q0 + wm * 16 + (lane >> 2);
        const int qr1 = qr0 + 8;

        for (int kt = 0; kt < nkt; ++kt) {
            const int k0 = kt * 64;
            __syncthreads();   // prev iter reads done (also covers Q fill at kt=0)
            {   // K tile: 64 keys x 128 bf16, stride 272
                const int row = tid >> 2, qb = tid & 3;
                const __nv_bfloat16* srch = g_kh + (size_t)(b * TN + k0 + row) * HN + qb * 32;
                const __nv_bfloat16* srcl = g_kl + (size_t)(b * TN + k0 + row) * HN + qb * 32;
#pragma unroll
                for (int i = 0; i < 4; ++i) {
                    *(uint4*)(smc + AK_H + row * 272 + qb * 64 + i * 16) = *(const uint4*)(srch + i * 8);
                    *(uint4*)(smc + AK_L + row * 272 + qb * 64 + i * 16) = *(const uint4*)(srcl + i * 8);
                }
                // V^T tile: 64 h-rows (this block's half) x 64 keys, stride 144
                const int vrow = tid >> 2, vq = tid & 3;
                const __nv_bfloat16* svh = g_vh + ((size_t)b * HN + hh * 64 + vrow) * TN + k0 + vq * 16;
                const __nv_bfloat16* svl = g_vl + ((size_t)b * HN + hh * 64 + vrow) * TN + k0 + vq * 16;
#pragma unroll
                for (int i = 0; i < 2; ++i) {
                    *(uint4*)(smc + AV_H + vrow * 144 + vq * 32 + i * 16) = *(const uint4*)(svh + i * 8);
                    *(uint4*)(smc + AV_L + vrow * 144 + vq * 32 + i * 16) = *(const uint4*)(svl + i * 8);
                }
            }
            __syncthreads();

            // ---- S = Q.K^T : warp = 16 rows x 32 keys, 3-pass split ----
            float s[4][4];
#pragma unroll
            for (int i = 0; i < 4; ++i)
#pragma unroll
                for (int j = 0; j < 4; ++j) s[i][j] = 0.f;
#pragma unroll
            for (int kk = 0; kk < 8; ++kk) {
                const int kb = kk * 32;
                uint32_t qh[4], ql[4];
                ldmx4(qh, sb + AQ_H + aAddr(wm * 16, kb, 272, lane));
                ldmx4(ql, sb + AQ_L + aAddr(wm * 16, kb, 272, lane));
#pragma unroll
                for (int np = 0; np < 2; ++np) {
                    uint32_t bh[4], bl[4];
                    ldmx4(bh, sb + AK_H + bAddr(wk * 32 + np * 16, kb, 272, lane));
                    ldmx4(bl, sb + AK_L + bAddr(wk * 32 + np * 16, kb, 272, lane));
                    mma_bf16(s[np * 2],     qh, bh);
                    mma_bf16(s[np * 2],     qh, bl);
                    mma_bf16(s[np * 2],     ql, bh);
                    mma_bf16(s[np * 2 + 1], qh, bh + 2);
                    mma_bf16(s[np * 2 + 1], qh, bl + 2);
                    mma_bf16(s[np * 2 + 1], ql, bh + 2);
                }
            }

            // ---- softmax (no max; bounded logits) + P frags ----
            uint32_t pH[2][4], pL[2][4];
#pragma unroll
            for (int j = 0; j < 4; ++j) {
                const int colb = k0 + wk * 32 + j * 8 + (lane & 3) * 2;
                float e0 = (colb     <= qr0) ? fex2(s[j][0] * SC) : 0.f;
                float e1 = (colb + 1 <= qr0) ? fex2(s[j][1] * SC) : 0.f;
                float e2 = (colb     <= qr1) ? fex2(s[j][2] * SC) : 0.f;
                float e3 = (colb + 1 <= qr1) ? fex2(s[j][3] * SC) : 0.f;
                ls0 += e0 + e1; ls1 += e2 + e3;
                const int kkf = j >> 1, hf = (j & 1) * 2;
                spl(e0, e1, pH[kkf][hf + 0], pL[kkf][hf + 0]);
                spl(e2, e3, pH[kkf][hf + 1], pL[kkf][hf + 1]);
            }

            // ---- O += P.V : 16 rows x 64 h (this block's half) ----
#pragma unroll
            for (int kkf = 0; kkf < 2; ++kkf) {
                const int kb = (wk * 32 + kkf * 16) * 2;
#pragma unroll
                for (int np = 0; np < 4; ++np) {
                    uint32_t vh[4], vl[4];
                    ldmx4(vh, sb + AV_H + bAddr(np * 16, kb, 144, lane));
                    ldmx4(vl, sb + AV_L + bAddr(np * 16, kb, 144, lane));
                    mma_bf16(o[np * 2],     pH[kkf], vh);
                    mma_bf16(o[np * 2],     pH[kkf], vl);
                    mma_bf16(o[np * 2],     pL[kkf], vh);
                    mma_bf16(o[np * 2 + 1], pH[kkf], vh + 2);
                    mma_bf16(o[np * 2 + 1], pH[kkf], vl + 2);
                    mma_bf16(o[np * 2 + 1], pL[kkf], vh + 2);
                }
            }
        }

        // ---- combine key-halves through smem, normalize, store ----
        ls0 += __shfl_xor_sync(0xffffffffu, ls0, 1);
        ls0 += __shfl_xor_sync(0xffffffffu, ls0, 2);
        ls1 += __shfl_xor_sync(0xffffffffu, ls1, 1);
        ls1 += __shfl_xor_sync(0xffffffffu, ls1, 2);

        __syncthreads();   // all warps done with K/V; reuse K region for partials
        {
            float* pO = (float*)(smc + AP_O) + wk * 64 * 64;
            float* pl = (float*)(smc + AP_L) + wk * 64;
            const int r0 = wm * 16 + (lane >> 2), r1 = r0 + 8;
#pragma unroll
            for (int ni = 0; ni < 8; ++ni) {
                const int col = ni * 8 + (lane & 3) * 2;
                *(float2*)&pO[r0 * 64 + col] = make_float2(o[ni][0], o[ni][1]);
                *(float2*)&pO[r1 * 64 + col] = make_float2(o[ni][2], o[ni][3]);
            }
            if ((lane & 3) == 0) { pl[r0] = ls0; pl[r1] = ls1; }
        }
        __syncthreads();
        {
            const float* p0 = (const float*)(smc + AP_O);
            const float* p1 = p0 + 64 * 64;
            const float* pl = (const float*)(smc + AP_L);
            const int row = tid >> 2, cb = (tid & 3) * 16;
            const float inv = 1.0f / (pl[row] + pl[64 + row]);
            float* orow = out + (size_t)(b * TN + q0 + row) * HN + hh * 64 + cb;
#pragma unroll
            for (int j = 0; j < 4; ++j) {
                float4 a = *(const float4*)&p0[row * 64 + cb + j * 4];
                float4 c = *(const float4*)&p1[row * 64 + cb + j * 4];
                *(float4*)(orow + j * 4) = make_float4((a.x + c.x) * inv, (a.y + c.y) * inv,
                                                       (a.z + c.z) * inv, (a.w + c.w) * inv);
            }
        }
        __syncthreads();   // partial reads done before next phase overwrites
    }
}

// ---------------------------------------------------------------------------
extern "C" void kernel_launch(void* const* d_in, const int* in_sizes, int n_in,
                              void* d_out, int out_size)
{
    const float* x  = (const float*)d_in[0];
    const float* Wk = (const float*)d_in[1];
    // d_in[2] = Wq — unused: reference computes q with Wk (source bug, kept faithfully)
    const float* Wv = (const float*)d_in[3];
    float* out = (float*)d_out;

    cudaFuncSetAttribute(proj_kernel, cudaFuncAttributeMaxDynamicSharedMemorySize, P_SMEM);
    cudaFuncSetAttribute(attn_kernel, cudaFuncAttributeMaxDynamicSharedMemorySize, A_SMEM);

    proj_kernel<<<dim3(128, 2), 256, P_SMEM>>>(x, Wk, Wv);
    attn_kernel<<<dim3(16, 2, BN), 256, A_SMEM>>>(out);
}

// round 17
// speedup vs baseline: 1.1771x; 1.1771x over previous
#include <cuda_runtime.h>
#include <cuda_bf16.h>
#include <cstdint>

#define BN 8
#define TN 2048
#define CN 1024
#define HN 128

// bf16 split scratch (allocation-free rule: __device__ globals)
__device__ __align__(16) __nv_bfloat16 g_kh[BN * TN * HN];   // k hi [b*T+t][h]  (q == k)
__device__ __align__(16) __nv_bfloat16 g_kl[BN * TN * HN];   // k lo
__device__ __align__(16) __nv_bfloat16 g_vh[BN * HN * TN];   // v^T hi [b][h][t]
__device__ __align__(16) __nv_bfloat16 g_vl[BN * HN * TN];   // v^T lo

// ---------------------------------------------------------------------------
__device__ __forceinline__ uint32_t smem_u32(const void* p) {
    uint32_t a;
    asm("{ .reg .u64 t; cvta.to.shared.u64 t, %1; cvt.u32.u64 %0, t; }" : "=r"(a) : "l"(p));
    return a;
}
__device__ __forceinline__ float fex2(float x) {
    float r; asm("ex2.approx.f32 %0, %1;" : "=f"(r) : "f"(x)); return r;
}
__device__ __forceinline__ void mma_bf16(float* d, const uint32_t* a, const uint32_t* b) {
    asm volatile("mma.sync.aligned.m16n8k16.row.col.f32.bf16.bf16.f32 "
        "{%0,%1,%2,%3}, {%4,%5,%6,%7}, {%8,%9}, {%0,%1,%2,%3};"
        : "+f"(d[0]), "+f"(d[1]), "+f"(d[2]), "+f"(d[3])
        : "r"(a[0]), "r"(a[1]), "r"(a[2]), "r"(a[3]), "r"(b[0]), "r"(b[1]));
}
__device__ __forceinline__ void ldmx4(uint32_t* r, uint32_t a) {
    asm volatile("ldmatrix.sync.aligned.m8n8.x4.shared.b16 {%0,%1,%2,%3}, [%4];"
        : "=r"(r[0]), "=r"(r[1]), "=r"(r[2]), "=r"(r[3]) : "r"(a));
}
__device__ __forceinline__ uint32_t aAddr(int r0, int kbyte, int stride, int lane) {
    int row = r0 + (lane & 7) + (lane & 8);
    int bo  = kbyte + ((lane >> 4) << 4);
    return (uint32_t)(row * stride + bo);
}
__device__ __forceinline__ uint32_t bAddr(int n0, int kbyte, int stride, int lane) {
    int row = n0 + (lane & 7) + ((lane & 16) >> 1);
    int bo  = kbyte + ((lane & 8) << 1);
    return (uint32_t)(row * stride + bo);
}
__device__ __forceinline__ void spl(float a, float b, uint32_t& H, uint32_t& L) {
    __nv_bfloat162 h = __floats2bfloat162_rn(a, b);
    H = *reinterpret_cast<uint32_t*>(&h);
    float ra = a - __bfloat162float(__low2bfloat16(h));
    float rb = b - __bfloat162float(__high2bfloat16(h));
    __nv_bfloat162 l = __floats2bfloat162_rn(ra, rb);
    L = *reinterpret_cast<uint32_t*>(&l);
}

// ---------------------------------------------------------------------------
// Projection (R8 known-good): grid (128, 2); 128 t-rows x 128 h of k (y=0) or
// v (y=1); in-kernel fp32->bf16 split; 3-pass mma over BK=32.
// ---------------------------------------------------------------------------
#define PX_H 0
#define PX_L 10240
#define PW_H 20480
#define PW_L 30720
#define P_STG 40960
#define P_SMEM (40960 + 128 * 132 * 4)   // 108544

__global__ __launch_bounds__(256, 2) void proj_kernel(
    const float* __restrict__ x,
    const float* __restrict__ Wk,
    const float* __restrict__ Wv)
{
    extern __shared__ char smc[];
    const uint32_t sb = smem_u32(smc);
    const int tid = threadIdx.x;
    const int lane = tid & 31, warp = tid >> 5;
    const int t0 = blockIdx.x * 128;
    const int mode = blockIdx.y;
    const float* __restrict__ W = (mode == 0) ? Wk : Wv;

    const int m0 = (warp >> 1) * 32;
    const int n0 = (warp & 1) * 64;

    float acc[2][8][4];
#pragma unroll
    for (int i = 0; i < 2; ++i)
#pragma unroll
        for (int j = 0; j < 8; ++j)
#pragma unroll
            for (int q = 0; q < 4; ++q) acc[i][j][q] = 0.f;

    const int frow = tid >> 1, fcb = (tid & 1) * 16;

    for (int c0 = 0; c0 < CN; c0 += 32) {
        __syncthreads();
        {
            const float* xr = x + (size_t)(t0 + frow) * CN + c0 + fcb;
            const float* wr = W + (size_t)frow * CN + c0 + fcb;
#pragma unroll
            for (int i = 0; i < 4; ++i) {
                float4 f = *(const float4*)(xr + i * 4);
                uint32_t h0, l0, h1, l1;
                spl(f.x, f.y, h0, l0); spl(f.z, f.w, h1, l1);
                *(uint2*)(smc + PX_H + frow * 80 + (fcb + i * 4) * 2) = make_uint2(h0, h1);
                *(uint2*)(smc + PX_L + frow * 80 + (fcb + i * 4) * 2) = make_uint2(l0, l1);
                f = *(const float4*)(wr + i * 4);
                spl(f.x, f.y, h0, l0); spl(f.z, f.w, h1, l1);
                *(uint2*)(smc + PW_H + frow * 80 + (fcb + i * 4) * 2) = make_uint2(h0, h1);
                *(uint2*)(smc + PW_L + frow * 80 + (fcb + i * 4) * 2) = make_uint2(l0, l1);
            }
        }
        __syncthreads();
#pragma unroll
        for (int kk = 0; kk < 2; ++kk) {
            const int kb = kk * 32;
            uint32_t ah[2][4], al[2][4];
            ldmx4(ah[0], sb + PX_H + aAddr(m0,      kb, 80, lane));
            ldmx4(ah[1], sb + PX_H + aAddr(m0 + 16, kb, 80, lane));
            ldmx4(al[0], sb + PX_L + aAddr(m0,      kb, 80, lane));
            ldmx4(al[1], sb + PX_L + aAddr(m0 + 16, kb, 80, lane));
#pragma unroll
            for (int np = 0; np < 4; ++np) {
                uint32_t bh[4], bl[4];
                ldmx4(bh, sb + PW_H + bAddr(n0 + np * 16, kb, 80, lane));
                ldmx4(bl, sb + PW_L + bAddr(n0 + np * 16, kb, 80, lane));
#pragma unroll
                for (int mi = 0; mi < 2; ++mi) {
                    mma_bf16(acc[mi][np * 2],     ah[mi], bh);
                    mma_bf16(acc[mi][np * 2],     ah[mi], bl);
                    mma_bf16(acc[mi][np * 2],     al[mi], bh);
                    mma_bf16(acc[mi][np * 2 + 1], ah[mi], bh + 2);
                    mma_bf16(acc[mi][np * 2 + 1], ah[mi], bl + 2);
                    mma_bf16(acc[mi][np * 2 + 1], al[mi], bh + 2);
                }
            }
        }
    }

    if (mode == 0) {
#pragma unroll
        for (int mi = 0; mi < 2; ++mi)
#pragma unroll
            for (int ni = 0; ni < 8; ++ni) {
                int gr  = t0 + m0 + mi * 16 + (lane >> 2);
                int col = n0 + ni * 8 + (lane & 3) * 2;
                uint32_t H, L;
                spl(acc[mi][ni][0], acc[mi][ni][1], H, L);
                *(uint32_t*)(g_kh + (size_t)gr * HN + col) = H;
                *(uint32_t*)(g_kl + (size_t)gr * HN + col) = L;
                spl(acc[mi][ni][2], acc[mi][ni][3], H, L);
                *(uint32_t*)(g_kh + (size_t)(gr + 8) * HN + col) = H;
                *(uint32_t*)(g_kl + (size_t)(gr + 8) * HN + col) = L;
            }
    } else {
        float* stg = (float*)(smc + P_STG);
#pragma unroll
        for (int mi = 0; mi < 2; ++mi)
#pragma unroll
            for (int ni = 0; ni < 8; ++ni) {
                int r = m0 + mi * 16 + (lane >> 2);
                int c = n0 + ni * 8 + (lane & 3) * 2;
                *(float2*)&stg[r * 132 + c]       = make_float2(acc[mi][ni][0], acc[mi][ni][1]);
                *(float2*)&stg[(r + 8) * 132 + c] = make_float2(acc[mi][ni][2], acc[mi][ni][3]);
            }
        __syncthreads();
        const int h = tid >> 1, th = (tid & 1) * 64;
        const int bb = t0 >> 11, tt0 = t0 & (TN - 1);
        __nv_bfloat16* dh = g_vh + ((size_t)bb * HN + h) * TN + tt0 + th;
        __nv_bfloat16* dl = g_vl + ((size_t)bb * HN + h) * TN + tt0 + th;
#pragma unroll
        for (int g = 0; g < 8; ++g) {
            uint32_t H[4], L[4];
#pragma unroll
            for (int j = 0; j < 4; ++j) {
                float a = stg[(th + g * 8 + j * 2) * 132 + h];
                float b = stg[(th + g * 8 + j * 2 + 1) * 132 + h];
                spl(a, b, H[j], L[j]);
            }
            *(uint4*)(dh + g * 8) = make_uint4(H[0], H[1], H[2], H[3]);
            *(uint4*)(dl + g * 8) = make_uint4(L[0], L[1], L[2], L[3]);
        }
    }
}

// ---------------------------------------------------------------------------
// Attention (R8 structure): balanced pairing, 33 iters/block, single-buffer
// fills. CHANGE vs R8: S uses 2-pass split (q_hi only; drops q_lo*k_hi term
// worth ~1.5e-4 output rel err). Q_lo never filled or loaded. PV stays 3-pass.
// ---------------------------------------------------------------------------
#define AQ_H 0
#define AK_H 17408
#define AK_L 34816
#define AV_H 52224
#define AV_L 70656
#define A_SMEM 89088
// epilogue partials overlay the K region:
#define AP_O  AK_H             // float [2][64][128] = 65536 B
#define AP_L  (AK_H + 65536)   // float [2][64]

__global__ __launch_bounds__(256, 1) void attn_kernel(float* __restrict__ out)
{
    extern __shared__ char smc[];
    const uint32_t sb = smem_u32(smc);
    const int tid = threadIdx.x;
    const int lane = tid & 31, warp = tid >> 5;
    const int wm = warp & 3;          // row group: q-rows 16*wm .. +15
    const int wk = warp >> 2;         // key half: keys 32*wk .. +31
    const int bx = blockIdx.x, b = blockIdx.y;
    const float SC = 1.4426950408889634f / 32.0f;   // log2(e) * C^-0.5

#pragma unroll 1
    for (int ph = 0; ph < 2; ++ph) {
        const int qt = ph ? bx : (31 - bx);
        const int q0 = qt * 64;
        const int nkt = qt + 1;

        // fill Q tile (hi only): 64 rows x 128 bf16, stride 272
        {
            const int row = tid >> 2, qb = tid & 3;
            const __nv_bfloat16* srch = g_kh + (size_t)(b * TN + q0 + row) * HN + qb * 32;
#pragma unroll
            for (int i = 0; i < 4; ++i)
                *(uint4*)(smc + AQ_H + row * 272 + qb * 64 + i * 16) = *(const uint4*)(srch + i * 8);
        }
        __syncthreads();

        // Q fragments resident (hi only): warp owns q-rows [wm*16, wm*16+16)
        uint32_t qfh[8][4];
#pragma unroll
        for (int kk = 0; kk < 8; ++kk)
            ldmx4(qfh[kk], sb + AQ_H + aAddr(wm * 16, kk * 32, 272, lane));

        float o[16][4];
#pragma unroll
        for (int i = 0; i < 16; ++i)
#pragma unroll
            for (int j = 0; j < 4; ++j) o[i][j] = 0.f;
        float ls0 = 0.f, ls1 = 0.f;
        const int qr0 = q0 + wm * 16 + (lane >> 2);
        const int qr1 = qr0 + 8;

        for (int kt = 0; kt < nkt; ++kt) {
            const int k0 = kt * 64;
            __syncthreads();    // prev iter's K/V reads complete
            {   // K tile: 64 keys x 128 bf16 hi/lo, stride 272
                const int row = tid >> 2, qb = tid & 3;
                const __nv_bfloat16* srch = g_kh + (size_t)(b * TN + k0 + row) * HN + qb * 32;
                const __nv_bfloat16* srcl = g_kl + (size_t)(b * TN + k0 + row) * HN + qb * 32;
#pragma unroll
                for (int i = 0; i < 4; ++i) {
                    *(uint4*)(smc + AK_H + row * 272 + qb * 64 + i * 16) = *(const uint4*)(srch + i * 8);
                    *(uint4*)(smc + AK_L + row * 272 + qb * 64 + i * 16) = *(const uint4*)(srcl + i * 8);
                }
                // V^T tile: 128 rows (h) x 64 keys, stride 144
                const int vrow = tid >> 1, vb2 = tid & 1;
                const __nv_bfloat16* svh = g_vh + ((size_t)b * HN + vrow) * TN + k0 + vb2 * 32;
                const __nv_bfloat16* svl = g_vl + ((size_t)b * HN + vrow) * TN + k0 + vb2 * 32;
#pragma unroll
                for (int i = 0; i < 4; ++i) {
                    *(uint4*)(smc + AV_H + vrow * 144 + vb2 * 64 + i * 16) = *(const uint4*)(svh + i * 8);
                    *(uint4*)(smc + AV_L + vrow * 144 + vb2 * 64 + i * 16) = *(const uint4*)(svl + i * 8);
                }
            }
            __syncthreads();

            // ---- S = Q.K^T : warp = 16 rows x 32 keys, 2-pass (hh + hl) ----
            float s[4][4];
#pragma unroll
            for (int i = 0; i < 4; ++i)
#pragma unroll
                for (int j = 0; j < 4; ++j) s[i][j] = 0.f;
#pragma unroll
            for (int kk = 0; kk < 8; ++kk) {
                const int kb = kk * 32;
#pragma unroll
                for (int np = 0; np < 2; ++np) {
                    uint32_t bh[4], bl[4];
                    ldmx4(bh, sb + AK_H + bAddr(wk * 32 + np * 16, kb, 272, lane));
                    ldmx4(bl, sb + AK_L + bAddr(wk * 32 + np * 16, kb, 272, lane));
                    mma_bf16(s[np * 2],     qfh[kk], bh);
                    mma_bf16(s[np * 2],     qfh[kk], bl);
                    mma_bf16(s[np * 2 + 1], qfh[kk], bh + 2);
                    mma_bf16(s[np * 2 + 1], qfh[kk], bl + 2);
                }
            }

            // ---- softmax (no max; bounded logits) + P frags ----
            uint32_t pH[2][4], pL[2][4];
#pragma unroll
            for (int j = 0; j < 4; ++j) {
                const int colb = k0 + wk * 32 + j * 8 + (lane & 3) * 2;
                float e0 = (colb     <= qr0) ? fex2(s[j][0] * SC) : 0.f;
                float e1 = (colb + 1 <= qr0) ? fex2(s[j][1] * SC) : 0.f;
                float e2 = (colb     <= qr1) ? fex2(s[j][2] * SC) : 0.f;
                float e3 = (colb + 1 <= qr1) ? fex2(s[j][3] * SC) : 0.f;
                ls0 += e0 + e1; ls1 += e2 + e3;
                const int kkf = j >> 1, hf = (j & 1) * 2;
                spl(e0, e1, pH[kkf][hf + 0], pL[kkf][hf + 0]);
                spl(e2, e3, pH[kkf][hf + 1], pL[kkf][hf + 1]);
            }

            // ---- O += P.V : 16 rows x 128 h, 3-pass ----
#pragma unroll
            for (int kkf = 0; kkf < 2; ++kkf) {
                const int kb = (wk * 32 + kkf * 16) * 2;
#pragma unroll
                for (int np = 0; np < 8; ++np) {
                    uint32_t vh[4], vl[4];
                    ldmx4(vh, sb + AV_H + bAddr(np * 16, kb, 144, lane));
                    ldmx4(vl, sb + AV_L + bAddr(np * 16, kb, 144, lane));
                    mma_bf16(o[np * 2],     pH[kkf], vh);
                    mma_bf16(o[np * 2],     pH[kkf], vl);
                    mma_bf16(o[np * 2],     pL[kkf], vh);
                    mma_bf16(o[np * 2 + 1], pH[kkf], vh + 2);
                    mma_bf16(o[np * 2 + 1], pH[kkf], vl + 2);
                    mma_bf16(o[np * 2 + 1], pL[kkf], vh + 2);
                }
            }
        }

        // ---- combine key-halves through smem, normalize, store ----
        ls0 += __shfl_xor_sync(0xffffffffu, ls0, 1);
        ls0 += __shfl_xor_sync(0xffffffffu, ls0, 2);
        ls1 += __shfl_xor_sync(0xffffffffu, ls1, 1);
        ls1 += __shfl_xor_sync(0xffffffffu, ls1, 2);

        __syncthreads();   // all warps done reading K/V; reuse K region
        {
            float* pO = (float*)(smc + AP_O) + wk * 64 * 128;
            float* pl = (float*)(smc + AP_L) + wk * 64;
            const int r0 = wm * 16 + (lane >> 2), r1 = r0 + 8;
#pragma unroll
            for (int ni = 0; ni < 16; ++ni) {
                const int col = ni * 8 + (lane & 3) * 2;
                *(float2*)&pO[r0 * 128 + col] = make_float2(o[ni][0], o[ni][1]);
                *(float2*)&pO[r1 * 128 + col] = make_float2(o[ni][2], o[ni][3]);
            }
            if ((lane & 3) == 0) { pl[r0] = ls0; pl[r1] = ls1; }
        }
        __syncthreads();
        {
            const float* p0 = (const float*)(smc + AP_O);
            const float* p1 = p0 + 64 * 128;
            const float* pl = (const float*)(smc + AP_L);
            const int row = tid >> 2, cb = (tid & 3) * 32;
            const float inv = 1.0f / (pl[row] + pl[64 + row]);
            float* orow = out + (size_t)(b * TN + q0 + row) * HN + cb;
#pragma unroll
            for (int j = 0; j < 8; ++j) {
                float4 a = *(const float4*)&p0[row * 128 + cb + j * 4];
                float4 c = *(const float4*)&p1[row * 128 + cb + j * 4];
                *(float4*)(orow + j * 4) = make_float4((a.x + c.x) * inv, (a.y + c.y) * inv,
                                                       (a.z + c.z) * inv, (a.w + c.w) * inv);
            }
        }
        __syncthreads();   // partial reads done before next phase's fills
    }
}

// ---------------------------------------------------------------------------
extern "C" void kernel_launch(void* const* d_in, const int* in_sizes, int n_in,
                              void* d_out, int out_size)
{
    const float* x  = (const float*)d_in[0];
    const float* Wk = (const float*)d_in[1];
    // d_in[2] = Wq — unused: reference computes q with Wk (source bug, kept faithfully)
    const float* Wv = (const float*)d_in[3];
    float* out = (float*)d_out;

    cudaFuncSetAttribute(proj_kernel, cudaFuncAttributeMaxDynamicSharedMemorySize, P_SMEM);
    cudaFuncSetAttribute(attn_kernel, cudaFuncAttributeMaxDynamicSharedMemorySize, A_SMEM);

    proj_kernel<<<dim3(128, 2), 256, P_SMEM>>>(x, Wk, Wv);
    attn_kernel<<<dim3(16, BN), 256, A_SMEM>>>(out);
}